// round 15
// baseline (speedup 1.0000x reference)
#include <cuda_runtime.h>
#include <cuda_bf16.h>
#include <cstdint>

// Problem constants
#define Bb 2
#define Ss 2048
#define Ee 1024
#define Hh 16
#define Dd 64
#define MM (Bb * Ss)   // 4096 rows

#define QSCALE 0.1803368801f   // 0.125 * log2(e)
#define MASKVAL (-14427.0f)    // -10000 * log2(e)

// ---------------------------------------------------------------------------
// Device-global scratch
// ---------------------------------------------------------------------------
__device__ __align__(128) __nv_bfloat16 g_Xh[MM * Ee],  g_Xl[MM * Ee];
__device__ __align__(128) __nv_bfloat16 g_Wqh[Ee * Ee], g_Wql[Ee * Ee];
__device__ __align__(128) __nv_bfloat16 g_Wkh[Ee * Ee], g_Wkl[Ee * Ee];
__device__ __align__(128) __nv_bfloat16 g_Wvh[Ee * Ee], g_Wvl[Ee * Ee];
__device__ __align__(128) __nv_bfloat16 g_Woh[Ee * Ee], g_Wol[Ee * Ee];
__device__ __align__(128) __nv_bfloat16 g_Qh[MM * Ee], g_Ql[MM * Ee];
__device__ __align__(128) __nv_bfloat16 g_Kh[MM * Ee], g_Kl[MM * Ee];
__device__ __align__(128) __nv_bfloat16 g_Vh[MM * Ee], g_Vl[MM * Ee];
__device__ __align__(128) __nv_bfloat16 g_Ah[MM * Ee], g_Al[MM * Ee];

// ---------------------------------------------------------------------------
// Helpers
// ---------------------------------------------------------------------------
__device__ __forceinline__ uint32_t smem_u32(const void* p) {
    return (uint32_t)__cvta_generic_to_shared(p);
}
__device__ __forceinline__ void ldsm4(uint32_t* r, uint32_t addr) {
    asm volatile("ldmatrix.sync.aligned.m8n8.x4.shared.b16 {%0,%1,%2,%3}, [%4];"
                 : "=r"(r[0]), "=r"(r[1]), "=r"(r[2]), "=r"(r[3]) : "r"(addr));
}
__device__ __forceinline__ void ldsm4t(uint32_t* r, uint32_t addr) {
    asm volatile("ldmatrix.sync.aligned.m8n8.x4.trans.shared.b16 {%0,%1,%2,%3}, [%4];"
                 : "=r"(r[0]), "=r"(r[1]), "=r"(r[2]), "=r"(r[3]) : "r"(addr));
}
__device__ __forceinline__ void mma_b2(float* c, const uint32_t* a, uint32_t b0, uint32_t b1) {
    asm volatile(
        "mma.sync.aligned.m16n8k16.row.col.f32.bf16.bf16.f32 "
        "{%0,%1,%2,%3}, {%4,%5,%6,%7}, {%8,%9}, {%0,%1,%2,%3};"
        : "+f"(c[0]), "+f"(c[1]), "+f"(c[2]), "+f"(c[3])
        : "r"(a[0]), "r"(a[1]), "r"(a[2]), "r"(a[3]), "r"(b0), "r"(b1));
}
__device__ __forceinline__ __nv_bfloat162 split_hi(float x0, float x1) {
    return __nv_bfloat162(__float2bfloat16(x0), __float2bfloat16(x1));
}
__device__ __forceinline__ __nv_bfloat162 split_lo(float x0, float x1) {
    float h0 = __bfloat162float(__float2bfloat16(x0));
    float h1 = __bfloat162float(__float2bfloat16(x1));
    return __nv_bfloat162(__float2bfloat16(x0 - h0), __float2bfloat16(x1 - h1));
}
__device__ __forceinline__ uint32_t pack_hi(float x0, float x1) {
    __nv_bfloat162 t = split_hi(x0, x1);
    return *(uint32_t*)&t;
}
__device__ __forceinline__ uint32_t pack_lo(float x0, float x1) {
    __nv_bfloat162 t = split_lo(x0, x1);
    return *(uint32_t*)&t;
}

// cp.async helpers
__device__ __forceinline__ void cp16(uint32_t dst, const void* src) {
    asm volatile("cp.async.cg.shared.global [%0], [%1], 16;"
                 :: "r"(dst), "l"(src) : "memory");
}
__device__ __forceinline__ void cp_commit() {
    asm volatile("cp.async.commit_group;" ::: "memory");
}
__device__ __forceinline__ void cp_wait0() {
    asm volatile("cp.async.wait_group 0;" ::: "memory");
}
__device__ __forceinline__ void cp_wait1() {
    asm volatile("cp.async.wait_group 1;" ::: "memory");
}
__device__ __forceinline__ void cp_wait2() {
    asm volatile("cp.async.wait_group 2;" ::: "memory");
}

// XOR swizzle for 128B-row tiles (attention)
__device__ __forceinline__ uint32_t swz(int r, int cb) {
    return (uint32_t)(r * 128 + (cb ^ ((r & 7) << 4)));
}
// XOR swizzle for 64B-row tiles (GEMM, BK=32). c4 = 16B-chunk index (0..3).
// Even rows occupy [0,64) of each 128B line, odd rows [64,128); chunk
// position XORed with (r>>1)&3 => 8 consecutive rows hit 8 distinct 16B banks.
__device__ __forceinline__ uint32_t swz32(int r, int c4) {
    return (uint32_t)(r * 64 + ((c4 ^ (r >> 1)) & 3) * 16);
}

// ---------------------------------------------------------------------------
// fp32 -> (hi, lo) bf16 split
// ---------------------------------------------------------------------------
__global__ __launch_bounds__(256) void split_kernel(
    const float* __restrict__ in, __nv_bfloat16* __restrict__ hi,
    __nv_bfloat16* __restrict__ lo, int n4)
{
    int i = blockIdx.x * blockDim.x + threadIdx.x;
    if (i >= n4) return;
    float4 v = ((const float4*)in)[i];
    ((__nv_bfloat162*)hi)[2 * i]     = split_hi(v.x, v.y);
    ((__nv_bfloat162*)hi)[2 * i + 1] = split_hi(v.z, v.w);
    ((__nv_bfloat162*)lo)[2 * i]     = split_lo(v.x, v.y);
    ((__nv_bfloat162*)lo)[2 * i + 1] = split_lo(v.z, v.w);
}

// ---------------------------------------------------------------------------
// Weight transpose + split
// ---------------------------------------------------------------------------
__global__ __launch_bounds__(256) void transpose_split_kernel(
    const float* __restrict__ W0, const float* __restrict__ W1,
    const float* __restrict__ W2, const float* __restrict__ W3)
{
    const float* W;
    __nv_bfloat16 *Th, *Tl;
    switch (blockIdx.z) {
        case 0:  W = W0; Th = g_Wqh; Tl = g_Wql; break;
        case 1:  W = W1; Th = g_Wkh; Tl = g_Wkl; break;
        case 2:  W = W2; Th = g_Wvh; Tl = g_Wvl; break;
        default: W = W3; Th = g_Woh; Tl = g_Wol; break;
    }
    __shared__ float t[32][33];
    const int n0 = blockIdx.x * 32;
    const int k0 = blockIdx.y * 32;
    const int tx = threadIdx.x, ty = threadIdx.y;
    #pragma unroll
    for (int i = 0; i < 4; i++) {
        int r = ty + i * 8;
        t[r][tx] = W[(size_t)(k0 + r) * Ee + n0 + tx];
    }
    __syncthreads();
    #pragma unroll
    for (int i = 0; i < 4; i++) {
        int r = ty + i * 8;
        float v = t[tx][r];
        float h = __bfloat162float(__float2bfloat16(v));
        size_t dst = (size_t)(n0 + r) * Ee + k0 + tx;
        Th[dst] = __float2bfloat16(v);
        Tl[dst] = __float2bfloat16(v - h);
    }
}

// ---------------------------------------------------------------------------
// Pipelined HMMA GEMM core, L2-traffic-optimized.
// Tile 128x128, BK=32, 3-stage cp.async, 512 threads = 16 warps (4m x 4n),
// warp tile 32x32, acc[2][4][4] = 32 regs. 1 CTA/SM (full RF: 512x128).
// SMEM stage (32KB): Ah@0, Al@8192, Bh@16384, Bl@24576. 3 stages = 96KB.
// ---------------------------------------------------------------------------
#define GP_STAGE 32768
#define GP_SMEM  (3 * GP_STAGE)
#define GP_NT    32             // K tiles: 1024/32

__device__ __forceinline__ void gemm_issue(
    uint32_t stg,
    const __nv_bfloat16* __restrict__ Ah, const __nv_bfloat16* __restrict__ Al,
    const __nv_bfloat16* __restrict__ Bh, const __nv_bfloat16* __restrict__ Bl,
    int row0, int col0, int kt, int tid)
{
    const int k0 = kt * 32;
    // A: 128 rows x 64B (hi + lo): 512 chunks each -> 1 per thread
    {
        int r = tid >> 2, c4 = tid & 3;
        size_t g = (size_t)(row0 + r) * Ee + k0 + c4 * 8;
        uint32_t d = swz32(r, c4);
        cp16(stg + d,        Ah + g);
        cp16(stg + 8192 + d, Al + g);
    }
    // B: 128 rows x 64B (hi + lo)
    {
        int r = tid >> 2, c4 = tid & 3;
        size_t g = (size_t)(col0 + r) * Ee + k0 + c4 * 8;
        uint32_t d = swz32(r, c4);
        cp16(stg + 16384 + d, Bh + g);
        cp16(stg + 24576 + d, Bl + g);
    }
    cp_commit();
}

__device__ __forceinline__ void gemm_pipeline(
    uint32_t sb,
    float acc[2][4][4],
    const __nv_bfloat16* __restrict__ Ah, const __nv_bfloat16* __restrict__ Al,
    const __nv_bfloat16* __restrict__ Bh, const __nv_bfloat16* __restrict__ Bl,
    int row0, int col0)
{
    const int tid  = threadIdx.x;
    const int lane = tid & 31;
    const int wid  = tid >> 5;
    const int warp_m = wid & 3;         // 0..3
    const int warp_n = wid >> 2;        // 0..3
    const int lrow   = lane & 15;
    const int lchunk = lane >> 4;       // 0 or 1 (16B chunk within k16)

    gemm_issue(sb,                Ah, Al, Bh, Bl, row0, col0, 0, tid);
    gemm_issue(sb + GP_STAGE,     Ah, Al, Bh, Bl, row0, col0, 1, tid);
    gemm_issue(sb + 2 * GP_STAGE, Ah, Al, Bh, Bl, row0, col0, 2, tid);

    int sidx = 0;
    for (int kt = 0; kt < GP_NT; kt++) {
        const uint32_t stg = sb + sidx * GP_STAGE;
        sidx = (sidx == 2) ? 0 : sidx + 1;
        cp_wait2();
        __syncthreads();

        #pragma unroll
        for (int ks = 0; ks < 2; ks++) {        // two k16 steps in BK=32
            const int c4 = ks * 2 + lchunk;
            uint32_t ah[2][4], al[2][4];
            #pragma unroll
            for (int mt = 0; mt < 2; mt++) {
                uint32_t off = swz32(warp_m * 32 + mt * 16 + lrow, c4);
                ldsm4(ah[mt], stg + off);
                ldsm4(al[mt], stg + 8192 + off);
            }
            uint32_t bh[2][4], bl[2][4];
            #pragma unroll
            for (int ng = 0; ng < 2; ng++) {
                uint32_t off = swz32(warp_n * 32 + ng * 16 + lrow, c4);
                ldsm4(bh[ng], stg + 16384 + off);
                ldsm4(bl[ng], stg + 24576 + off);
            }
            #pragma unroll
            for (int mt = 0; mt < 2; mt++) {
                #pragma unroll
                for (int ng = 0; ng < 2; ng++) {
                    mma_b2(acc[mt][2 * ng],     ah[mt], bh[ng][0], bh[ng][2]);
                    mma_b2(acc[mt][2 * ng],     ah[mt], bl[ng][0], bl[ng][2]);
                    mma_b2(acc[mt][2 * ng],     al[mt], bh[ng][0], bh[ng][2]);
                    mma_b2(acc[mt][2 * ng + 1], ah[mt], bh[ng][1], bh[ng][3]);
                    mma_b2(acc[mt][2 * ng + 1], ah[mt], bl[ng][1], bl[ng][3]);
                    mma_b2(acc[mt][2 * ng + 1], al[mt], bh[ng][1], bh[ng][3]);
                }
            }
        }
        __syncthreads();
        if (kt + 3 < GP_NT)
            gemm_issue(stg, Ah, Al, Bh, Bl, row0, col0, kt + 3, tid);
        else
            cp_commit();
    }
}

// ---------------------------------------------------------------------------
// QKV projection. Q output pre-scaled by 0.125*log2(e).
// grid=(8, 32, 3), block 512. BN=128 spans two heads.
// ---------------------------------------------------------------------------
__global__ __launch_bounds__(512, 1)
void gemm_qkv_kernel(const float* __restrict__ bq, const float* __restrict__ bk,
                     const float* __restrict__ bv)
{
    extern __shared__ char smem[];
    const __nv_bfloat16 *Wh, *Wl;
    __nv_bfloat16 *Dh, *Dl;
    const float* bias;
    float oscale;
    if (blockIdx.z == 0)      { Wh = g_Wqh; Wl = g_Wql; Dh = g_Qh; Dl = g_Ql; bias = bq; oscale = QSCALE; }
    else if (blockIdx.z == 1) { Wh = g_Wkh; Wl = g_Wkl; Dh = g_Kh; Dl = g_Kl; bias = bk; oscale = 1.f; }
    else                      { Wh = g_Wvh; Wl = g_Wvl; Dh = g_Vh; Dl = g_Vl; bias = bv; oscale = 1.f; }

    const int row0 = blockIdx.y * 128;
    const int col0 = blockIdx.x * 128;

    float acc[2][4][4];
    #pragma unroll
    for (int mt = 0; mt < 2; mt++)
        #pragma unroll
        for (int j = 0; j < 4; j++)
            #pragma unroll
            for (int r = 0; r < 4; r++) acc[mt][j][r] = 0.f;

    gemm_pipeline(smem_u32(smem), acc, g_Xh, g_Xl, Wh, Wl, row0, col0);

    const int lane = threadIdx.x & 31;
    const int wid  = threadIdx.x >> 5;
    const int warp_m = wid & 3, warp_n = wid >> 2;
    #pragma unroll
    for (int mt = 0; mt < 2; mt++) {
        int erow = row0 + warp_m * 32 + mt * 16 + (lane >> 2);
        int b = erow >> 11, sI = erow & (Ss - 1);
        #pragma unroll
        for (int nt = 0; nt < 4; nt++) {
            int gc = col0 + warp_n * 32 + (nt >> 1) * 16 + (nt & 1) * 8 + (lane & 3) * 2;
            int h = gc >> 6, d = gc & 63;
            float b0 = bias[gc], b1 = bias[gc + 1];
            float x0 = (acc[mt][nt][0] + b0) * oscale, x1 = (acc[mt][nt][1] + b1) * oscale;
            float y0 = (acc[mt][nt][2] + b0) * oscale, y1 = (acc[mt][nt][3] + b1) * oscale;
            size_t d0 = ((size_t)((b << 4) + h) * Ss + sI) * Dd + d;
            size_t d1 = d0 + 8 * Dd;
            *(__nv_bfloat162*)&Dh[d0] = split_hi(x0, x1);
            *(__nv_bfloat162*)&Dl[d0] = split_lo(x0, x1);
            *(__nv_bfloat162*)&Dh[d1] = split_hi(y0, y1);
            *(__nv_bfloat162*)&Dl[d1] = split_lo(y0, y1);
        }
    }
}

// ---------------------------------------------------------------------------
// Output projection. grid=(8, 32), block 512.
// ---------------------------------------------------------------------------
__global__ __launch_bounds__(512, 1)
void gemm_out_kernel(const float* __restrict__ bias, float* __restrict__ C)
{
    extern __shared__ char smem[];
    const int row0 = blockIdx.y * 128;
    const int col0 = blockIdx.x * 128;

    float acc[2][4][4];
    #pragma unroll
    for (int mt = 0; mt < 2; mt++)
        #pragma unroll
        for (int j = 0; j < 4; j++)
            #pragma unroll
            for (int r = 0; r < 4; r++) acc[mt][j][r] = 0.f;

    gemm_pipeline(smem_u32(smem), acc, g_Ah, g_Al, g_Woh, g_Wol, row0, col0);

    const int lane = threadIdx.x & 31;
    const int wid  = threadIdx.x >> 5;
    const int warp_m = wid & 3, warp_n = wid >> 2;
    #pragma unroll
    for (int mt = 0; mt < 2; mt++) {
        int erow = row0 + warp_m * 32 + mt * 16 + (lane >> 2);
        #pragma unroll
        for (int nt = 0; nt < 4; nt++) {
            int gc = col0 + warp_n * 32 + (nt >> 1) * 16 + (nt & 1) * 8 + (lane & 3) * 2;
            float b0 = bias[gc], b1 = bias[gc + 1];
            *(float2*)(C + (size_t)erow * Ee + gc) =
                make_float2(acc[mt][nt][0] + b0, acc[mt][nt][1] + b1);
            *(float2*)(C + (size_t)(erow + 8) * Ee + gc) =
                make_float2(acc[mt][nt][2] + b0, acc[mt][nt][3] + b1);
        }
    }
}

// ---------------------------------------------------------------------------
// Causal flash attention, bf16x3, BQ=128, fixed-shift softmax (unchanged R11).
// grid=(8, B*H), block 256, SMEM 64KB (2x32KB stages), paired q-tiles.
// ---------------------------------------------------------------------------
#define AT_STAGE 32768
#define AT_SMEM  (2 * AT_STAGE)

__device__ __forceinline__ void attn_issue(
    uint32_t stg,
    const __nv_bfloat16* khB, const __nv_bfloat16* klB,
    const __nv_bfloat16* vhB, const __nv_bfloat16* vlB,
    int kt, int tid)
{
    #pragma unroll
    for (int it = 0; it < 2; it++) {
        int idx = tid + it * 256;
        int r = idx >> 3, cq = idx & 7;
        size_t g = (size_t)(kt * 64 + r) * Dd + cq * 8;
        uint32_t d = swz(r, cq * 16);
        cp16(stg + d,         khB + g);
        cp16(stg + 8192 + d,  klB + g);
        cp16(stg + 16384 + d, vhB + g);
        cp16(stg + 24576 + d, vlB + g);
    }
    cp_commit();
}

__global__ __launch_bounds__(256, 2) void attn_tc_kernel()
{
    extern __shared__ char smem[];
    const uint32_t sb = smem_u32(smem);

    const int tid  = threadIdx.x;
    const int lane = tid & 31;
    const int warp = tid >> 5;
    const int bh = blockIdx.y;

    const size_t hbase = (size_t)bh * Ss * Dd;
    const __nv_bfloat16* qhB = g_Qh + hbase;
    const __nv_bfloat16* qlB = g_Ql + hbase;
    const __nv_bfloat16* khB = g_Kh + hbase;
    const __nv_bfloat16* klB = g_Kl + hbase;
    const __nv_bfloat16* vhB = g_Vh + hbase;
    const __nv_bfloat16* vlB = g_Vl + hbase;

    const int lrow = lane & 15;
    const int lcb  = ((lane >> 4) * 8) * 2;

    #pragma unroll 1
    for (int half = 0; half < 2; half++) {
        const int qt = half ? (15 - (int)blockIdx.x) : (int)blockIdx.x;
        const int q0 = qt * 128;
        const int ntiles = 2 * qt + 2;

        cp_wait0();
        __syncthreads();

        #pragma unroll
        for (int it = 0; it < 4; it++) {
            int idx = tid + it * 256;
            int r = idx >> 3, cq = idx & 7;
            size_t g = (size_t)(q0 + r) * Dd + cq * 8;
            *(uint4*)(smem + swz(r, cq * 16))         = *(const uint4*)(qhB + g);
            *(uint4*)(smem + 16384 + swz(r, cq * 16)) = *(const uint4*)(qlB + g);
        }
        __syncthreads();
        uint32_t qh[4][4], ql[4][4];
        #pragma unroll
        for (int ks = 0; ks < 4; ks++) {
            uint32_t off = swz(warp * 16 + lrow, ks * 32 + lcb);
            ldsm4(qh[ks], sb + off);
            ldsm4(ql[ks], sb + 16384 + off);
        }
        __syncthreads();

        attn_issue(sb, khB, klB, vhB, vlB, 0, tid);
        if (ntiles > 1) attn_issue(sb + AT_STAGE, khB, klB, vhB, vlB, 1, tid);
        else cp_commit();

        float o[8][4];
        #pragma unroll
        for (int nt = 0; nt < 8; nt++)
            #pragma unroll
            for (int r = 0; r < 4; r++) o[nt][r] = 0.f;
        float l0 = 0.f, l1 = 0.f;

        for (int kt = 0; kt < ntiles; kt++) {
            const uint32_t stg = sb + (kt & 1) * AT_STAGE;
            cp_wait1();
            __syncthreads();

            float s[8][4];
            #pragma unroll
            for (int nt = 0; nt < 8; nt++)
                #pragma unroll
                for (int r = 0; r < 4; r++) s[nt][r] = 0.f;

            #pragma unroll
            for (int kg = 0; kg < 4; kg++) {
                #pragma unroll
                for (int ks = 0; ks < 4; ks++) {
                    uint32_t kh[4], kl[4];
                    uint32_t off = swz(kg * 16 + lrow, ks * 32 + lcb);
                    ldsm4(kh, stg + off);
                    ldsm4(kl, stg + 8192 + off);
                    mma_b2(s[2 * kg],     qh[ks], kh[0], kh[2]);
                    mma_b2(s[2 * kg],     qh[ks], kl[0], kl[2]);
                    mma_b2(s[2 * kg],     ql[ks], kh[0], kh[2]);
                    mma_b2(s[2 * kg + 1], qh[ks], kh[1], kh[3]);
                    mma_b2(s[2 * kg + 1], qh[ks], kl[1], kl[3]);
                    mma_b2(s[2 * kg + 1], ql[ks], kh[1], kh[3]);
                }
            }

            if (kt >= 2 * qt) {
                int qg0 = q0 + warp * 16 + (lane >> 2);
                int qg1 = qg0 + 8;
                #pragma unroll
                for (int nt = 0; nt < 8; nt++) {
                    int kg = kt * 64 + nt * 8 + 2 * (lane & 3);
                    if (kg     > qg0) s[nt][0] = MASKVAL;
                    if (kg + 1 > qg0) s[nt][1] = MASKVAL;
                    if (kg     > qg1) s[nt][2] = MASKVAL;
                    if (kg + 1 > qg1) s[nt][3] = MASKVAL;
                }
            }

            float rs0 = 0.f, rs1 = 0.f;
            #pragma unroll
            for (int nt = 0; nt < 8; nt++) {
                s[nt][0] = exp2f(s[nt][0]);
                s[nt][1] = exp2f(s[nt][1]);
                s[nt][2] = exp2f(s[nt][2]);
                s[nt][3] = exp2f(s[nt][3]);
                rs0 += s[nt][0] + s[nt][1];
                rs1 += s[nt][2] + s[nt][3];
            }
            rs0 += __shfl_xor_sync(0xffffffffu, rs0, 1);
            rs0 += __shfl_xor_sync(0xffffffffu, rs0, 2);
            rs1 += __shfl_xor_sync(0xffffffffu, rs1, 1);
            rs1 += __shfl_xor_sync(0xffffffffu, rs1, 2);
            l0 += rs0;
            l1 += rs1;

            uint32_t ph[4][4], pl[4][4];
            #pragma unroll
            for (int kk = 0; kk < 4; kk++) {
                int t0 = 2 * kk, t1 = 2 * kk + 1;
                ph[kk][0] = pack_hi(s[t0][0], s[t0][1]);
                ph[kk][1] = pack_hi(s[t0][2], s[t0][3]);
                ph[kk][2] = pack_hi(s[t1][0], s[t1][1]);
                ph[kk][3] = pack_hi(s[t1][2], s[t1][3]);
                pl[kk][0] = pack_lo(s[t0][0], s[t0][1]);
                pl[kk][1] = pack_lo(s[t0][2], s[t0][3]);
                pl[kk][2] = pack_lo(s[t1][0], s[t1][1]);
                pl[kk][3] = pack_lo(s[t1][2], s[t1][3]);
            }

            #pragma unroll
            for (int kk = 0; kk < 4; kk++) {
                #pragma unroll
                for (int g = 0; g < 4; g++) {
                    uint32_t vh[4], vl[4];
                    uint32_t off = swz(kk * 16 + lrow, g * 32 + lcb);
                    ldsm4t(vh, stg + 16384 + off);
                    ldsm4t(vl, stg + 24576 + off);
                    mma_b2(o[2 * g],     ph[kk], vh[0], vh[1]);
                    mma_b2(o[2 * g],     ph[kk], vl[0], vl[1]);
                    mma_b2(o[2 * g],     pl[kk], vh[0], vh[1]);
                    mma_b2(o[2 * g + 1], ph[kk], vh[2], vh[3]);
                    mma_b2(o[2 * g + 1], ph[kk], vl[2], vl[3]);
                    mma_b2(o[2 * g + 1], pl[kk], vh[2], vh[3]);
                }
            }

            __syncthreads();
            if (kt + 2 < ntiles)
                attn_issue(stg, khB, klB, vhB, vlB, kt + 2, tid);
            else
                cp_commit();
        }

        const float inv0 = 1.f / l0;
        const float inv1 = 1.f / l1;
        const int b = bh >> 4;
        const int h = bh & 15;
        const int row0 = b * Ss + q0 + warp * 16 + (lane >> 2);
        const int col0 = h * Dd + 2 * (lane & 3);
        #pragma unroll
        for (int nt = 0; nt < 8; nt++) {
            int c = col0 + nt * 8;
            float x0 = o[nt][0] * inv0, x1 = o[nt][1] * inv0;
            float y0 = o[nt][2] * inv1, y1 = o[nt][3] * inv1;
            size_t d0 = (size_t)row0 * Ee + c;
            size_t d1 = (size_t)(row0 + 8) * Ee + c;
            *(__nv_bfloat162*)&g_Ah[d0] = split_hi(x0, x1);
            *(__nv_bfloat162*)&g_Al[d0] = split_lo(x0, x1);
            *(__nv_bfloat162*)&g_Ah[d1] = split_hi(y0, y1);
            *(__nv_bfloat162*)&g_Al[d1] = split_lo(y0, y1);
        }
    }
}

// ---------------------------------------------------------------------------
extern "C" void kernel_launch(void* const* d_in, const int* in_sizes, int n_in,
                              void* d_out, int out_size)
{
    const float* x  = (const float*)d_in[0];
    const float* Wq = (const float*)d_in[1];
    const float* bq = (const float*)d_in[2];
    const float* Wk = (const float*)d_in[3];
    const float* bk = (const float*)d_in[4];
    const float* Wv = (const float*)d_in[5];
    const float* bv = (const float*)d_in[6];
    const float* Wo = (const float*)d_in[7];
    const float* bo = (const float*)d_in[8];
    float* out = (float*)d_out;

    __nv_bfloat16 *Xh, *Xl;
    cudaGetSymbolAddress((void**)&Xh, g_Xh);
    cudaGetSymbolAddress((void**)&Xl, g_Xl);

    cudaFuncSetAttribute(gemm_qkv_kernel,
                         cudaFuncAttributeMaxDynamicSharedMemorySize, GP_SMEM);
    cudaFuncSetAttribute(gemm_out_kernel,
                         cudaFuncAttributeMaxDynamicSharedMemorySize, GP_SMEM);
    cudaFuncSetAttribute(attn_tc_kernel,
                         cudaFuncAttributeMaxDynamicSharedMemorySize, AT_SMEM);

    const int nX4 = MM * Ee / 4;
    split_kernel<<<(nX4 + 255) / 256, 256>>>(x, Xh, Xl, nX4);
    transpose_split_kernel<<<dim3(32, 32, 4), dim3(32, 8)>>>(Wq, Wk, Wv, Wo);

    gemm_qkv_kernel<<<dim3(8, 32, 3), 512, GP_SMEM>>>(bq, bk, bv);

    attn_tc_kernel<<<dim3(8, Bb * Hh), 256, AT_SMEM>>>();

    gemm_out_kernel<<<dim3(8, 32), 512, GP_SMEM>>>(bo, out);
}

// round 17
// speedup vs baseline: 1.2034x; 1.2034x over previous
#include <cuda_runtime.h>
#include <cuda_bf16.h>
#include <cstdint>

// Problem constants
#define Bb 2
#define Ss 2048
#define Ee 1024
#define Hh 16
#define Dd 64
#define MM (Bb * Ss)   // 4096 rows

#define QSCALE 0.1803368801f   // 0.125 * log2(e)
#define MASKVAL (-14427.0f)    // -10000 * log2(e)

// ---------------------------------------------------------------------------
// Device-global scratch
// ---------------------------------------------------------------------------
__device__ __align__(128) __nv_bfloat16 g_Xh[MM * Ee],  g_Xl[MM * Ee];
__device__ __align__(128) __nv_bfloat16 g_Wqh[Ee * Ee], g_Wql[Ee * Ee];
__device__ __align__(128) __nv_bfloat16 g_Wkh[Ee * Ee], g_Wkl[Ee * Ee];
__device__ __align__(128) __nv_bfloat16 g_Wvh[Ee * Ee], g_Wvl[Ee * Ee];
__device__ __align__(128) __nv_bfloat16 g_Woh[Ee * Ee], g_Wol[Ee * Ee];
__device__ __align__(128) __nv_bfloat16 g_Qh[MM * Ee], g_Ql[MM * Ee];
__device__ __align__(128) __nv_bfloat16 g_Kh[MM * Ee], g_Kl[MM * Ee];
__device__ __align__(128) __nv_bfloat16 g_Vh[MM * Ee], g_Vl[MM * Ee];
__device__ __align__(128) __nv_bfloat16 g_Ah[MM * Ee], g_Al[MM * Ee];

// ---------------------------------------------------------------------------
// Helpers
// ---------------------------------------------------------------------------
__device__ __forceinline__ uint32_t smem_u32(const void* p) {
    return (uint32_t)__cvta_generic_to_shared(p);
}
__device__ __forceinline__ void ldsm4(uint32_t* r, uint32_t addr) {
    asm volatile("ldmatrix.sync.aligned.m8n8.x4.shared.b16 {%0,%1,%2,%3}, [%4];"
                 : "=r"(r[0]), "=r"(r[1]), "=r"(r[2]), "=r"(r[3]) : "r"(addr));
}
__device__ __forceinline__ void ldsm4t(uint32_t* r, uint32_t addr) {
    asm volatile("ldmatrix.sync.aligned.m8n8.x4.trans.shared.b16 {%0,%1,%2,%3}, [%4];"
                 : "=r"(r[0]), "=r"(r[1]), "=r"(r[2]), "=r"(r[3]) : "r"(addr));
}
__device__ __forceinline__ void mma_b2(float* c, const uint32_t* a, uint32_t b0, uint32_t b1) {
    asm volatile(
        "mma.sync.aligned.m16n8k16.row.col.f32.bf16.bf16.f32 "
        "{%0,%1,%2,%3}, {%4,%5,%6,%7}, {%8,%9}, {%0,%1,%2,%3};"
        : "+f"(c[0]), "+f"(c[1]), "+f"(c[2]), "+f"(c[3])
        : "r"(a[0]), "r"(a[1]), "r"(a[2]), "r"(a[3]), "r"(b0), "r"(b1));
}
__device__ __forceinline__ __nv_bfloat162 split_hi(float x0, float x1) {
    return __nv_bfloat162(__float2bfloat16(x0), __float2bfloat16(x1));
}
__device__ __forceinline__ __nv_bfloat162 split_lo(float x0, float x1) {
    float h0 = __bfloat162float(__float2bfloat16(x0));
    float h1 = __bfloat162float(__float2bfloat16(x1));
    return __nv_bfloat162(__float2bfloat16(x0 - h0), __float2bfloat16(x1 - h1));
}
// guaranteed single-MUFU exp2
__device__ __forceinline__ float ex2(float x) {
    float r; asm("ex2.approx.ftz.f32 %0, %1;" : "=f"(r) : "f"(x)); return r;
}
// truncation-based hi pack: 1 PRMT packs the two fp32 high halves as bf16x2
__device__ __forceinline__ uint32_t prmt_hi(float x0, float x1) {
    uint32_t r;
    asm("prmt.b32 %0, %1, %2, 0x7632;" : "=r"(r)
        : "r"(__float_as_uint(x0)), "r"(__float_as_uint(x1)));
    return r;
}
// compensated residual of truncation, packed bf16x2 (low=x0 residual)
__device__ __forceinline__ uint32_t pack_lo_tr(float x0, float x1) {
    float l0 = x0 - __uint_as_float(__float_as_uint(x0) & 0xFFFF0000u);
    float l1 = x1 - __uint_as_float(__float_as_uint(x1) & 0xFFFF0000u);
    uint32_t r;
    asm("cvt.rn.bf16x2.f32 %0, %1, %2;" : "=r"(r) : "f"(l1), "f"(l0));
    return r;
}

// cp.async helpers
__device__ __forceinline__ void cp16(uint32_t dst, const void* src) {
    asm volatile("cp.async.cg.shared.global [%0], [%1], 16;"
                 :: "r"(dst), "l"(src) : "memory");
}
__device__ __forceinline__ void cp_commit() {
    asm volatile("cp.async.commit_group;" ::: "memory");
}
__device__ __forceinline__ void cp_wait0() {
    asm volatile("cp.async.wait_group 0;" ::: "memory");
}
__device__ __forceinline__ void cp_wait1() {
    asm volatile("cp.async.wait_group 1;" ::: "memory");
}
__device__ __forceinline__ void cp_wait2() {
    asm volatile("cp.async.wait_group 2;" ::: "memory");
}

// XOR swizzle for 128B-row tiles
__device__ __forceinline__ uint32_t swz(int r, int cb) {
    return (uint32_t)(r * 128 + (cb ^ ((r & 7) << 4)));
}

// ---------------------------------------------------------------------------
// fp32 -> (hi, lo) bf16 split
// ---------------------------------------------------------------------------
__global__ __launch_bounds__(256) void split_kernel(
    const float* __restrict__ in, __nv_bfloat16* __restrict__ hi,
    __nv_bfloat16* __restrict__ lo, int n4)
{
    int i = blockIdx.x * blockDim.x + threadIdx.x;
    if (i >= n4) return;
    float4 v = ((const float4*)in)[i];
    ((__nv_bfloat162*)hi)[2 * i]     = split_hi(v.x, v.y);
    ((__nv_bfloat162*)hi)[2 * i + 1] = split_hi(v.z, v.w);
    ((__nv_bfloat162*)lo)[2 * i]     = split_lo(v.x, v.y);
    ((__nv_bfloat162*)lo)[2 * i + 1] = split_lo(v.z, v.w);
}

// ---------------------------------------------------------------------------
// Weight transpose + split
// ---------------------------------------------------------------------------
__global__ __launch_bounds__(256) void transpose_split_kernel(
    const float* __restrict__ W0, const float* __restrict__ W1,
    const float* __restrict__ W2, const float* __restrict__ W3)
{
    const float* W;
    __nv_bfloat16 *Th, *Tl;
    switch (blockIdx.z) {
        case 0:  W = W0; Th = g_Wqh; Tl = g_Wql; break;
        case 1:  W = W1; Th = g_Wkh; Tl = g_Wkl; break;
        case 2:  W = W2; Th = g_Wvh; Tl = g_Wvl; break;
        default: W = W3; Th = g_Woh; Tl = g_Wol; break;
    }
    __shared__ float t[32][33];
    const int n0 = blockIdx.x * 32;
    const int k0 = blockIdx.y * 32;
    const int tx = threadIdx.x, ty = threadIdx.y;
    #pragma unroll
    for (int i = 0; i < 4; i++) {
        int r = ty + i * 8;
        t[r][tx] = W[(size_t)(k0 + r) * Ee + n0 + tx];
    }
    __syncthreads();
    #pragma unroll
    for (int i = 0; i < 4; i++) {
        int r = ty + i * 8;
        float v = t[tx][r];
        float h = __bfloat162float(__float2bfloat16(v));
        size_t dst = (size_t)(n0 + r) * Ee + k0 + tx;
        Th[dst] = __float2bfloat16(v);
        Tl[dst] = __float2bfloat16(v - h);
    }
}

// ---------------------------------------------------------------------------
// Pipelined HMMA GEMM core (R11 proven config — do not touch).
// Tile 128x64, BK=64, 2-stage cp.async, 256 threads, 2 CTA/SM.
// ---------------------------------------------------------------------------
#define GP_STAGE 49152
#define GP_SMEM  (2 * GP_STAGE)
#define GP_NT    16

__device__ __forceinline__ void gemm_issue(
    uint32_t stg,
    const __nv_bfloat16* __restrict__ Ah, const __nv_bfloat16* __restrict__ Al,
    const __nv_bfloat16* __restrict__ Bh, const __nv_bfloat16* __restrict__ Bl,
    int row0, int col0, int kt, int tid)
{
    const int k0 = kt * 64;
    #pragma unroll
    for (int it = 0; it < 4; it++) {            // A: 128 rows x 128B, hi+lo
        int idx = tid + it * 256;
        int r = idx >> 3, cq = idx & 7;
        size_t g = (size_t)(row0 + r) * Ee + k0 + cq * 8;
        uint32_t d = swz(r, cq * 16);
        cp16(stg + d,         Ah + g);
        cp16(stg + 16384 + d, Al + g);
    }
    #pragma unroll
    for (int it = 0; it < 2; it++) {            // B: 64 rows x 128B, hi+lo
        int idx = tid + it * 256;
        int r = idx >> 3, cq = idx & 7;
        size_t g = (size_t)(col0 + r) * Ee + k0 + cq * 8;
        uint32_t d = swz(r, cq * 16);
        cp16(stg + 32768 + d, Bh + g);
        cp16(stg + 40960 + d, Bl + g);
    }
    cp_commit();
}

__device__ __forceinline__ void gemm_pipeline(
    uint32_t sb,
    float acc[2][4][4],
    const __nv_bfloat16* __restrict__ Ah, const __nv_bfloat16* __restrict__ Al,
    const __nv_bfloat16* __restrict__ Bh, const __nv_bfloat16* __restrict__ Bl,
    int row0, int col0)
{
    const int tid  = threadIdx.x;
    const int lane = tid & 31;
    const int wid  = tid >> 5;
    const int warp_m = wid & 3;
    const int warp_n = wid >> 2;
    const int lrow  = lane & 15;
    const int lcb   = ((lane >> 4) * 8) * 2;

    gemm_issue(sb,            Ah, Al, Bh, Bl, row0, col0, 0, tid);
    gemm_issue(sb + GP_STAGE, Ah, Al, Bh, Bl, row0, col0, 1, tid);

    for (int kt = 0; kt < GP_NT; kt++) {
        const uint32_t stg = sb + (kt & 1) * GP_STAGE;
        cp_wait1();
        __syncthreads();

        #pragma unroll
        for (int ks = 0; ks < 4; ks++) {
            uint32_t ah[2][4], al[2][4];
            #pragma unroll
            for (int mt = 0; mt < 2; mt++) {
                uint32_t off = swz(warp_m * 32 + mt * 16 + lrow, ks * 32 + lcb);
                ldsm4(ah[mt], stg + off);
                ldsm4(al[mt], stg + 16384 + off);
            }
            uint32_t bh[2][4], bl[2][4];
            #pragma unroll
            for (int ng = 0; ng < 2; ng++) {
                uint32_t off = swz(warp_n * 32 + ng * 16 + lrow, ks * 32 + lcb);
                ldsm4(bh[ng], stg + 32768 + off);
                ldsm4(bl[ng], stg + 40960 + off);
            }
            #pragma unroll
            for (int mt = 0; mt < 2; mt++) {
                #pragma unroll
                for (int ng = 0; ng < 2; ng++) {
                    mma_b2(acc[mt][2 * ng],     ah[mt], bh[ng][0], bh[ng][2]);
                    mma_b2(acc[mt][2 * ng],     ah[mt], bl[ng][0], bl[ng][2]);
                    mma_b2(acc[mt][2 * ng],     al[mt], bh[ng][0], bh[ng][2]);
                    mma_b2(acc[mt][2 * ng + 1], ah[mt], bh[ng][1], bh[ng][3]);
                    mma_b2(acc[mt][2 * ng + 1], ah[mt], bl[ng][1], bl[ng][3]);
                    mma_b2(acc[mt][2 * ng + 1], al[mt], bh[ng][1], bh[ng][3]);
                }
            }
        }
        __syncthreads();
        if (kt + 2 < GP_NT)
            gemm_issue(stg, Ah, Al, Bh, Bl, row0, col0, kt + 2, tid);
        else
            cp_commit();
    }
}

// ---------------------------------------------------------------------------
// QKV projection. Q output pre-scaled by 0.125*log2(e).
// grid=(16, 32, 3), block 256. BN=64 == one head.
// ---------------------------------------------------------------------------
__global__ __launch_bounds__(256, 2)
void gemm_qkv_kernel(const float* __restrict__ bq, const float* __restrict__ bk,
                     const float* __restrict__ bv)
{
    extern __shared__ char smem[];
    const __nv_bfloat16 *Wh, *Wl;
    __nv_bfloat16 *Dh, *Dl;
    const float* bias;
    float oscale;
    if (blockIdx.z == 0)      { Wh = g_Wqh; Wl = g_Wql; Dh = g_Qh; Dl = g_Ql; bias = bq; oscale = QSCALE; }
    else if (blockIdx.z == 1) { Wh = g_Wkh; Wl = g_Wkl; Dh = g_Kh; Dl = g_Kl; bias = bk; oscale = 1.f; }
    else                      { Wh = g_Wvh; Wl = g_Wvl; Dh = g_Vh; Dl = g_Vl; bias = bv; oscale = 1.f; }

    const int row0 = blockIdx.y * 128;
    const int col0 = blockIdx.x * 64;

    float acc[2][4][4];
    #pragma unroll
    for (int mt = 0; mt < 2; mt++)
        #pragma unroll
        for (int j = 0; j < 4; j++)
            #pragma unroll
            for (int r = 0; r < 4; r++) acc[mt][j][r] = 0.f;

    gemm_pipeline(smem_u32(smem), acc, g_Xh, g_Xl, Wh, Wl, row0, col0);

    const int lane = threadIdx.x & 31;
    const int wid  = threadIdx.x >> 5;
    const int warp_m = wid & 3, warp_n = wid >> 2;
    const int h = col0 >> 6;
    #pragma unroll
    for (int mt = 0; mt < 2; mt++) {
        int erow = row0 + warp_m * 32 + mt * 16 + (lane >> 2);
        int b = erow >> 11, sI = erow & (Ss - 1);
        #pragma unroll
        for (int nt = 0; nt < 4; nt++) {
            int gc = col0 + warp_n * 32 + nt * 8 + (lane & 3) * 2;
            int d = gc & 63;
            float b0 = bias[gc], b1 = bias[gc + 1];
            float x0 = (acc[mt][nt][0] + b0) * oscale, x1 = (acc[mt][nt][1] + b1) * oscale;
            float y0 = (acc[mt][nt][2] + b0) * oscale, y1 = (acc[mt][nt][3] + b1) * oscale;
            size_t d0 = ((size_t)((b << 4) + h) * Ss + sI) * Dd + d;
            size_t d1 = d0 + 8 * Dd;
            *(__nv_bfloat162*)&Dh[d0] = split_hi(x0, x1);
            *(__nv_bfloat162*)&Dl[d0] = split_lo(x0, x1);
            *(__nv_bfloat162*)&Dh[d1] = split_hi(y0, y1);
            *(__nv_bfloat162*)&Dl[d1] = split_lo(y0, y1);
        }
    }
}

// ---------------------------------------------------------------------------
// Output projection. grid=(16, 32), block 256.
// ---------------------------------------------------------------------------
__global__ __launch_bounds__(256, 2)
void gemm_out_kernel(const float* __restrict__ bias, float* __restrict__ C)
{
    extern __shared__ char smem[];
    const int row0 = blockIdx.y * 128;
    const int col0 = blockIdx.x * 64;

    float acc[2][4][4];
    #pragma unroll
    for (int mt = 0; mt < 2; mt++)
        #pragma unroll
        for (int j = 0; j < 4; j++)
            #pragma unroll
            for (int r = 0; r < 4; r++) acc[mt][j][r] = 0.f;

    gemm_pipeline(smem_u32(smem), acc, g_Ah, g_Al, g_Woh, g_Wol, row0, col0);

    const int lane = threadIdx.x & 31;
    const int wid  = threadIdx.x >> 5;
    const int warp_m = wid & 3, warp_n = wid >> 2;
    #pragma unroll
    for (int mt = 0; mt < 2; mt++) {
        int erow = row0 + warp_m * 32 + mt * 16 + (lane >> 2);
        #pragma unroll
        for (int nt = 0; nt < 4; nt++) {
            int gc = col0 + warp_n * 32 + nt * 8 + (lane & 3) * 2;
            float b0 = bias[gc], b1 = bias[gc + 1];
            *(float2*)(C + (size_t)erow * Ee + gc) =
                make_float2(acc[mt][nt][0] + b0, acc[mt][nt][1] + b1);
            *(float2*)(C + (size_t)(erow + 8) * Ee + gc) =
                make_float2(acc[mt][nt][2] + b0, acc[mt][nt][3] + b1);
        }
    }
}

// ---------------------------------------------------------------------------
// Causal flash attention, bf16x3, BQ=128, fixed-shift softmax, 3-stage
// cp.async K/V pipeline, ex2.approx + truncation pack. Paired q-tiles.
// grid=(8, B*H), block 256, SMEM 96KB (3x32KB stages), 2 CTA/SM.
// ---------------------------------------------------------------------------
#define AT_STAGE 32768
#define AT_SMEM  (3 * AT_STAGE)

__device__ __forceinline__ void attn_issue(
    uint32_t stg,
    const __nv_bfloat16* khB, const __nv_bfloat16* klB,
    const __nv_bfloat16* vhB, const __nv_bfloat16* vlB,
    int kt, int tid)
{
    #pragma unroll
    for (int it = 0; it < 2; it++) {
        int idx = tid + it * 256;
        int r = idx >> 3, cq = idx & 7;
        size_t g = (size_t)(kt * 64 + r) * Dd + cq * 8;
        uint32_t d = swz(r, cq * 16);
        cp16(stg + d,         khB + g);
        cp16(stg + 8192 + d,  klB + g);
        cp16(stg + 16384 + d, vhB + g);
        cp16(stg + 24576 + d, vlB + g);
    }
    cp_commit();
}

__global__ __launch_bounds__(256, 2) void attn_tc_kernel()
{
    extern __shared__ char smem[];
    const uint32_t sb = smem_u32(smem);

    const int tid  = threadIdx.x;
    const int lane = tid & 31;
    const int warp = tid >> 5;
    const int bh = blockIdx.y;

    const size_t hbase = (size_t)bh * Ss * Dd;
    const __nv_bfloat16* qhB = g_Qh + hbase;
    const __nv_bfloat16* qlB = g_Ql + hbase;
    const __nv_bfloat16* khB = g_Kh + hbase;
    const __nv_bfloat16* klB = g_Kl + hbase;
    const __nv_bfloat16* vhB = g_Vh + hbase;
    const __nv_bfloat16* vlB = g_Vl + hbase;

    const int lrow = lane & 15;
    const int lcb  = ((lane >> 4) * 8) * 2;

    #pragma unroll 1
    for (int half = 0; half < 2; half++) {
        const int qt = half ? (15 - (int)blockIdx.x) : (int)blockIdx.x;
        const int q0 = qt * 128;
        const int ntiles = 2 * qt + 2;

        // drain all pending cp.async before reusing stage smem for Q
        cp_wait0();
        __syncthreads();

        // ---- Stage Q (128x64 hi/lo) in stage0 area, load A-frags ----
        #pragma unroll
        for (int it = 0; it < 4; it++) {
            int idx = tid + it * 256;
            int r = idx >> 3, cq = idx & 7;
            size_t g = (size_t)(q0 + r) * Dd + cq * 8;
            *(uint4*)(smem + swz(r, cq * 16))         = *(const uint4*)(qhB + g);
            *(uint4*)(smem + 16384 + swz(r, cq * 16)) = *(const uint4*)(qlB + g);
        }
        __syncthreads();
        uint32_t qh[4][4], ql[4][4];
        #pragma unroll
        for (int ks = 0; ks < 4; ks++) {
            uint32_t off = swz(warp * 16 + lrow, ks * 32 + lcb);
            ldsm4(qh[ks], sb + off);
            ldsm4(ql[ks], sb + 16384 + off);
        }
        __syncthreads();   // all warps done reading Q before cp.async overwrites

        // prologue: fill 3 stages (dummy commits keep group count uniform)
        attn_issue(sb,                khB, klB, vhB, vlB, 0, tid);
        attn_issue(sb + AT_STAGE,     khB, klB, vhB, vlB, 1, tid);
        if (ntiles > 2) attn_issue(sb + 2 * AT_STAGE, khB, klB, vhB, vlB, 2, tid);
        else cp_commit();

        float o[8][4];
        #pragma unroll
        for (int nt = 0; nt < 8; nt++)
            #pragma unroll
            for (int r = 0; r < 4; r++) o[nt][r] = 0.f;
        float l0 = 0.f, l1 = 0.f;

        int sidx = 0;
        for (int kt = 0; kt < ntiles; kt++) {
            const uint32_t stg = sb + sidx * AT_STAGE;
            sidx = (sidx == 2) ? 0 : sidx + 1;
            cp_wait2();
            __syncthreads();

            // ---- S = Q @ K^T (bf16x3), log2 domain ----
            float s[8][4];
            #pragma unroll
            for (int nt = 0; nt < 8; nt++)
                #pragma unroll
                for (int r = 0; r < 4; r++) s[nt][r] = 0.f;

            #pragma unroll
            for (int kg = 0; kg < 4; kg++) {
                #pragma unroll
                for (int ks = 0; ks < 4; ks++) {
                    uint32_t kh[4], kl[4];
                    uint32_t off = swz(kg * 16 + lrow, ks * 32 + lcb);
                    ldsm4(kh, stg + off);
                    ldsm4(kl, stg + 8192 + off);
                    mma_b2(s[2 * kg],     qh[ks], kh[0], kh[2]);
                    mma_b2(s[2 * kg],     qh[ks], kl[0], kl[2]);
                    mma_b2(s[2 * kg],     ql[ks], kh[0], kh[2]);
                    mma_b2(s[2 * kg + 1], qh[ks], kh[1], kh[3]);
                    mma_b2(s[2 * kg + 1], qh[ks], kl[1], kl[3]);
                    mma_b2(s[2 * kg + 1], ql[ks], kh[1], kh[3]);
                }
            }

            if (kt >= 2 * qt) {                  // diagonal-crossing key tiles
                int qg0 = q0 + warp * 16 + (lane >> 2);
                int qg1 = qg0 + 8;
                #pragma unroll
                for (int nt = 0; nt < 8; nt++) {
                    int kg = kt * 64 + nt * 8 + 2 * (lane & 3);
                    if (kg     > qg0) s[nt][0] = MASKVAL;
                    if (kg + 1 > qg0) s[nt][1] = MASKVAL;
                    if (kg     > qg1) s[nt][2] = MASKVAL;
                    if (kg + 1 > qg1) s[nt][3] = MASKVAL;
                }
            }

            // ---- fixed-shift softmax: p = 2^s via single-MUFU ex2 ----
            float rs0 = 0.f, rs1 = 0.f;
            #pragma unroll
            for (int nt = 0; nt < 8; nt++) {
                s[nt][0] = ex2(s[nt][0]);
                s[nt][1] = ex2(s[nt][1]);
                s[nt][2] = ex2(s[nt][2]);
                s[nt][3] = ex2(s[nt][3]);
                rs0 += s[nt][0] + s[nt][1];
                rs1 += s[nt][2] + s[nt][3];
            }
            rs0 += __shfl_xor_sync(0xffffffffu, rs0, 1);
            rs0 += __shfl_xor_sync(0xffffffffu, rs0, 2);
            rs1 += __shfl_xor_sync(0xffffffffu, rs1, 1);
            rs1 += __shfl_xor_sync(0xffffffffu, rs1, 2);
            l0 += rs0;
            l1 += rs1;

            // ---- pack P: truncation hi (PRMT) + compensated lo ----
            uint32_t ph[4][4], pl[4][4];
            #pragma unroll
            for (int kk = 0; kk < 4; kk++) {
                int t0 = 2 * kk, t1 = 2 * kk + 1;
                ph[kk][0] = prmt_hi(s[t0][0], s[t0][1]);
                pl[kk][0] = pack_lo_tr(s[t0][0], s[t0][1]);
                ph[kk][1] = prmt_hi(s[t0][2], s[t0][3]);
                pl[kk][1] = pack_lo_tr(s[t0][2], s[t0][3]);
                ph[kk][2] = prmt_hi(s[t1][0], s[t1][1]);
                pl[kk][2] = pack_lo_tr(s[t1][0], s[t1][1]);
                ph[kk][3] = prmt_hi(s[t1][2], s[t1][3]);
                pl[kk][3] = pack_lo_tr(s[t1][2], s[t1][3]);
            }

            // ---- O += P @ V (bf16x3) ----
            #pragma unroll
            for (int kk = 0; kk < 4; kk++) {
                #pragma unroll
                for (int g = 0; g < 4; g++) {
                    uint32_t vh[4], vl[4];
                    uint32_t off = swz(kk * 16 + lrow, g * 32 + lcb);
                    ldsm4t(vh, stg + 16384 + off);
                    ldsm4t(vl, stg + 24576 + off);
                    mma_b2(o[2 * g],     ph[kk], vh[0], vh[1]);
                    mma_b2(o[2 * g],     ph[kk], vl[0], vl[1]);
                    mma_b2(o[2 * g],     pl[kk], vh[0], vh[1]);
                    mma_b2(o[2 * g + 1], ph[kk], vh[2], vh[3]);
                    mma_b2(o[2 * g + 1], ph[kk], vl[2], vl[3]);
                    mma_b2(o[2 * g + 1], pl[kk], vh[2], vh[3]);
                }
            }

            __syncthreads();
            if (kt + 3 < ntiles)
                attn_issue(stg, khB, klB, vhB, vlB, kt + 3, tid);
            else
                cp_commit();
        }

        // ---- epilogue for this q-tile ----
        const float inv0 = 1.f / l0;
        const float inv1 = 1.f / l1;
        const int b = bh >> 4;
        const int h = bh & 15;
        const int row0 = b * Ss + q0 + warp * 16 + (lane >> 2);
        const int col0 = h * Dd + 2 * (lane & 3);
        #pragma unroll
        for (int nt = 0; nt < 8; nt++) {
            int c = col0 + nt * 8;
            float x0 = o[nt][0] * inv0, x1 = o[nt][1] * inv0;
            float y0 = o[nt][2] * inv1, y1 = o[nt][3] * inv1;
            size_t d0 = (size_t)row0 * Ee + c;
            size_t d1 = (size_t)(row0 + 8) * Ee + c;
            *(__nv_bfloat162*)&g_Ah[d0] = split_hi(x0, x1);
            *(__nv_bfloat162*)&g_Al[d0] = split_lo(x0, x1);
            *(__nv_bfloat162*)&g_Ah[d1] = split_hi(y0, y1);
            *(__nv_bfloat162*)&g_Al[d1] = split_lo(y0, y1);
        }
    }
}

// ---------------------------------------------------------------------------
extern "C" void kernel_launch(void* const* d_in, const int* in_sizes, int n_in,
                              void* d_out, int out_size)
{
    const float* x  = (const float*)d_in[0];
    const float* Wq = (const float*)d_in[1];
    const float* bq = (const float*)d_in[2];
    const float* Wk = (const float*)d_in[3];
    const float* bk = (const float*)d_in[4];
    const float* Wv = (const float*)d_in[5];
    const float* bv = (const float*)d_in[6];
    const float* Wo = (const float*)d_in[7];
    const float* bo = (const float*)d_in[8];
    float* out = (float*)d_out;

    __nv_bfloat16 *Xh, *Xl;
    cudaGetSymbolAddress((void**)&Xh, g_Xh);
    cudaGetSymbolAddress((void**)&Xl, g_Xl);

    cudaFuncSetAttribute(gemm_qkv_kernel,
                         cudaFuncAttributeMaxDynamicSharedMemorySize, GP_SMEM);
    cudaFuncSetAttribute(gemm_out_kernel,
                         cudaFuncAttributeMaxDynamicSharedMemorySize, GP_SMEM);
    cudaFuncSetAttribute(attn_tc_kernel,
                         cudaFuncAttributeMaxDynamicSharedMemorySize, AT_SMEM);

    const int nX4 = MM * Ee / 4;
    split_kernel<<<(nX4 + 255) / 256, 256>>>(x, Xh, Xl, nX4);
    transpose_split_kernel<<<dim3(32, 32, 4), dim3(32, 8)>>>(Wq, Wk, Wv, Wo);

    gemm_qkv_kernel<<<dim3(16, 32, 3), 256, GP_SMEM>>>(bq, bk, bv);

    attn_tc_kernel<<<dim3(8, Bb * Hh), 256, AT_SMEM>>>();

    gemm_out_kernel<<<dim3(16, 32), 256, GP_SMEM>>>(bo, out);
}